// round 1
// baseline (speedup 1.0000x reference)
#include <cuda_runtime.h>
#include <math.h>

#define NP 131072   // 64*64*32 voxels
#define CH 96

// ---- scratch (static device arrays; no allocation allowed) ----
__device__ float  d_h [CH*NP];          // [c][x][y][z]
__device__ float  d_x2[CH*NP];          // skip-conv output
__device__ float2 d_S1[CH*64*64*8];     // after z-DFT   [c][x][y][kz]
__device__ float2 d_S2[CH*64*16*8];     // after y-DFT   [c][x][ky][kz]
__device__ float2 d_S3[CH*16*16*8];     // after x-DFT   [c][kx][ky][kz]
__device__ float2 d_G [CH*16*16*8];     // mode-mixed    [o][kx][ky][kz]
__device__ float2 d_T2[CH*64*16*8];     // inv x         [o][x][ky][kz]
__device__ float2 d_T1[CH*64*64*8];     // inv y         [o][x][y][kz]
__device__ float2 d_tw[64];             // e^{-2pi i r/64}

__global__ void k_tw() {
    int t = threadIdx.x;
    float s, c;
    sincospif(t * (2.0f / 64.0f), &s, &c);
    d_tw[t] = make_float2(c, -s);       // e^{-2*pi*i*t/64}
}

// ---- fc0: [p][nt][nvar] + grid -> h[c][p] ----
__global__ void k_fc0(const float* __restrict__ x, const float* __restrict__ w,
                      const float* __restrict__ b, float* __restrict__ h) {
    __shared__ float vsh[64 * 29];
    __shared__ float wsh[28 * 96];
    __shared__ float bsh[96];
    int t = threadIdx.x;                 // 256
    int p0 = blockIdx.x * 64;
    for (int idx = t; idx < 64 * 25; idx += 256) {
        int p = idx / 25, j = idx % 25;
        int nv = j / 5, nt = j % 5;      // v[nv*5+nt] = x[p,nt,nv]
        vsh[p * 29 + j] = x[(p0 + p) * 25 + nt * 5 + nv];
    }
    if (t < 192) {
        int p = t % 64, j = t / 64;
        int pg = p0 + p;
        float g;
        if (j == 0)      g = (float)(pg >> 11)        * (1.0f / 63.0f);
        else if (j == 1) g = (float)((pg >> 5) & 63)  * (1.0f / 63.0f);
        else             g = (float)(pg & 31)         * (1.0f / 31.0f);
        vsh[p * 29 + 25 + j] = g;
    }
    for (int idx = t; idx < 28 * 96; idx += 256) wsh[idx] = w[idx];
    if (t < 96) bsh[t] = b[t];
    __syncthreads();
    int p = t & 63;
    for (int c = t >> 6; c < 96; c += 4) {
        float acc = bsh[c];
        #pragma unroll
        for (int j = 0; j < 28; j++) acc = fmaf(vsh[p * 29 + j], wsh[j * 96 + c], acc);
        h[c * NP + p0 + p] = acc;
    }
}

// ---- forward z-DFT: h[c][x][y][0..31] -> S1[c][x][y][kz<8] ----
__global__ void k_fwdZ(const float* __restrict__ h, float2* __restrict__ S1) {
    __shared__ float sh[64 * 33];
    __shared__ float2 tws[64];
    int t = threadIdx.x;                 // 256
    int cx = blockIdx.x;                 // c*64 + x
    const float* row = h + (long)cx * 2048;
    for (int idx = t; idx < 2048; idx += 256) sh[(idx >> 5) * 33 + (idx & 31)] = row[idx];
    if (t < 64) tws[t] = d_tw[t];
    __syncthreads();
    int kz = t & 7, y0 = t >> 3;         // y0 0..31
    #pragma unroll
    for (int half = 0; half < 2; half++) {
        int y = y0 + 32 * half;
        float re = 0.f, im = 0.f;
        #pragma unroll
        for (int z = 0; z < 32; z++) {
            float v = sh[y * 33 + z];
            float2 w = tws[(2 * kz * z) & 63];
            re = fmaf(v, w.x, re);
            im = fmaf(v, w.y, im);
        }
        S1[((long)cx * 64 + y) * 8 + kz] = make_float2(re, im);
    }
}

// ---- forward y-DFT (16 kept ky) ----
__global__ void k_fwdY(const float2* __restrict__ S1, float2* __restrict__ S2) {
    __shared__ float2 sh[64 * 8];
    __shared__ float2 tws[64];
    int t = threadIdx.x;                 // 128
    int cx = blockIdx.x;
    const float2* src = S1 + (long)cx * 512;
    for (int idx = t; idx < 512; idx += 128) sh[idx] = src[idx];
    if (t < 64) tws[t] = d_tw[t];
    __syncthreads();
    int kz = t & 7, ky = t >> 3;         // ky 0..15
    int kye = (ky < 8) ? ky : ky + 48;
    float re = 0.f, im = 0.f;
    #pragma unroll
    for (int y = 0; y < 64; y++) {
        float2 v = sh[y * 8 + kz];
        float2 w = tws[(kye * y) & 63];
        re += v.x * w.x - v.y * w.y;
        im += v.x * w.y + v.y * w.x;
    }
    S2[((long)cx * 16 + ky) * 8 + kz] = make_float2(re, im);
}

// ---- forward x-DFT (16 kept kx) ----
__global__ void k_fwdX(const float2* __restrict__ S2, float2* __restrict__ S3) {
    __shared__ float2 sh[64 * 16];
    __shared__ float2 tws[64];
    int t = threadIdx.x;                 // 256
    int c = blockIdx.x >> 3, kz = blockIdx.x & 7;
    for (int idx = t; idx < 1024; idx += 256) {
        int x = idx >> 4, ky = idx & 15;
        sh[idx] = S2[(((long)c * 64 + x) * 16 + ky) * 8 + kz];
    }
    if (t < 64) tws[t] = d_tw[t];
    __syncthreads();
    int kx = t >> 4, ky = t & 15;
    int kxe = (kx < 8) ? kx : kx + 48;
    float re = 0.f, im = 0.f;
    for (int x = 0; x < 64; x++) {
        float2 v = sh[x * 16 + ky];
        float2 w = tws[(kxe * x) & 63];
        re += v.x * w.x - v.y * w.y;
        im += v.x * w.y + v.y * w.x;
    }
    S3[(((long)c * 16 + kx) * 16 + ky) * 8 + kz] = make_float2(re, im);
}

// ---- mode mix: G[o,m] = sum_i S3[i,m] * W[corner,i,o,m]  (complex) ----
__global__ void k_mix(const float2* __restrict__ S3, const float* __restrict__ wspec,
                      float2* __restrict__ G) {
    __shared__ float2 sh[8 * 512];
    int t = threadIdx.x;                 // 256
    int o = blockIdx.x % 96;
    int corner = blockIdx.x / 96;
    int kx0 = (corner & 1) * 8, ky0 = (corner >> 1) * 8;
    float2 acc0 = make_float2(0.f, 0.f), acc1 = make_float2(0.f, 0.f);
    int m0 = t, m1 = t + 256;
    for (int i0 = 0; i0 < 96; i0 += 8) {
        for (int idx = t; idx < 8 * 512; idx += 256) {
            int ii = idx >> 9, m = idx & 511;
            int a = m >> 6, rem = m & 63;
            sh[idx] = S3[((((long)(i0 + ii) * 16) + kx0 + a) * 16 + ky0) * 8 + rem];
        }
        __syncthreads();
        const float* wbase = wspec + (((long)(corner * 96 + i0) * 96) + o) * 1024;
        #pragma unroll
        for (int ii = 0; ii < 8; ii++) {
            const float2* wrow = (const float2*)(wbase + (long)ii * 96 * 1024);
            float2 s0 = sh[ii * 512 + m0];
            float2 w0 = __ldg(&wrow[m0]);
            acc0.x += s0.x * w0.x - s0.y * w0.y;
            acc0.y += s0.x * w0.y + s0.y * w0.x;
            float2 s1 = sh[ii * 512 + m1];
            float2 w1 = __ldg(&wrow[m1]);
            acc1.x += s1.x * w1.x - s1.y * w1.y;
            acc1.y += s1.x * w1.y + s1.y * w1.x;
        }
        __syncthreads();
    }
    int a = m0 >> 6, bb = (m0 >> 3) & 7, kz = m0 & 7;
    G[(((long)o * 16 + kx0 + a) * 16 + ky0 + bb) * 8 + kz] = acc0;
    a = m1 >> 6; bb = (m1 >> 3) & 7; kz = m1 & 7;
    G[(((long)o * 16 + kx0 + a) * 16 + ky0 + bb) * 8 + kz] = acc1;
}

// ---- inverse x (e^{+i}) ----
__global__ void k_invX(const float2* __restrict__ G, float2* __restrict__ T2) {
    __shared__ float2 sh[256];
    __shared__ float2 tws[64];
    int t = threadIdx.x;                 // 256
    int o = blockIdx.x >> 3, kz = blockIdx.x & 7;
    {
        int kx = t >> 4, ky = t & 15;
        sh[t] = G[(((long)o * 16 + kx) * 16 + ky) * 8 + kz];
    }
    if (t < 64) tws[t] = d_tw[t];
    __syncthreads();
    int ky = t & 15, x0 = t >> 4;
    #pragma unroll
    for (int pp = 0; pp < 4; pp++) {
        int x = x0 + 16 * pp;
        float re = 0.f, im = 0.f;
        #pragma unroll
        for (int kx = 0; kx < 16; kx++) {
            int kxe = (kx < 8) ? kx : kx + 48;
            float2 v = sh[kx * 16 + ky];
            float2 w = tws[(kxe * x) & 63];     // conj -> e^{+i}
            re += v.x * w.x + v.y * w.y;
            im += v.y * w.x - v.x * w.y;
        }
        T2[(((long)o * 64 + x) * 16 + ky) * 8 + kz] = make_float2(re, im);
    }
}

// ---- inverse y (e^{+i}), fold 1/(XYZ) and the kz weight ----
__global__ void k_invY(const float2* __restrict__ T2, float2* __restrict__ T1) {
    __shared__ float2 sh[128];
    __shared__ float2 tws[64];
    int t = threadIdx.x;                 // 256
    int ox = blockIdx.x;
    if (t < 128) sh[t] = T2[(long)ox * 128 + t];
    if (t >= 128 && t < 192) tws[t - 128] = d_tw[t - 128];
    __syncthreads();
    int kz = t & 7, y0 = t >> 3;         // y0 0..31
    #pragma unroll
    for (int half = 0; half < 2; half++) {
        int y = y0 + 32 * half;
        float re = 0.f, im = 0.f;
        #pragma unroll
        for (int ky = 0; ky < 16; ky++) {
            int kye = (ky < 8) ? ky : ky + 48;
            float2 v = sh[ky * 8 + kz];
            float2 w = tws[(kye * y) & 63];
            re += v.x * w.x + v.y * w.y;
            im += v.y * w.x - v.x * w.y;
        }
        float sc = (kz == 0) ? (1.0f / 131072.0f) : (2.0f / 131072.0f);
        T1[((long)ox * 64 + y) * 8 + kz] = make_float2(re * sc, im * sc);
    }
}

// ---- skip 1x1 conv: x2[o][p] = sum_i W[o][i] h[i][p] + b[o] ----
__global__ void k_skip(const float* __restrict__ h, const float* __restrict__ W,
                       const float* __restrict__ b, float* __restrict__ x2) {
    __shared__ float hsh[96 * 128];      // 48KB
    int t = threadIdx.x;                 // 256
    int p0 = blockIdx.x * 128;
    for (int idx = t; idx < 96 * 128; idx += 256)
        hsh[idx] = h[(long)(idx >> 7) * NP + p0 + (idx & 127)];
    __syncthreads();
    int tx = t & 31, ty = t >> 5;
    float acc[12][4];
    #pragma unroll
    for (int a = 0; a < 12; a++)
        #pragma unroll
        for (int bb = 0; bb < 4; bb++) acc[a][bb] = 0.f;
    for (int i = 0; i < 96; i++) {
        float hv[4];
        #pragma unroll
        for (int pp = 0; pp < 4; pp++) hv[pp] = hsh[i * 128 + tx + 32 * pp];
        #pragma unroll
        for (int oo = 0; oo < 12; oo++) {
            float wv = __ldg(&W[(ty + 8 * oo) * 96 + i]);
            #pragma unroll
            for (int pp = 0; pp < 4; pp++) acc[oo][pp] = fmaf(wv, hv[pp], acc[oo][pp]);
        }
    }
    #pragma unroll
    for (int oo = 0; oo < 12; oo++) {
        int o = ty + 8 * oo;
        float bv = __ldg(&b[o]);
        #pragma unroll
        for (int pp = 0; pp < 4; pp++)
            x2[(long)o * NP + p0 + tx + 32 * pp] = acc[oo][pp] + bv;
    }
}

// ---- inverse z + skip add + (gelu): writes h in place ----
__global__ void k_invZ(const float2* __restrict__ T1, const float* __restrict__ x2,
                       float* __restrict__ h, int do_gelu) {
    __shared__ float2 sh[64 * 8];
    __shared__ float2 tws[64];
    int t = threadIdx.x;                 // 256
    int ox = blockIdx.x;
    for (int idx = t; idx < 512; idx += 256) sh[idx] = T1[(long)ox * 512 + idx];
    if (t < 64) tws[t] = d_tw[t];
    __syncthreads();
    int z = t & 31, yg = t >> 5;
    float2 tz[8];
    #pragma unroll
    for (int kz = 0; kz < 8; kz++) tz[kz] = tws[(2 * kz * z) & 63];
    const float* x2row = x2 + (long)ox * 2048;
    float* hrow = h + (long)ox * 2048;
    #pragma unroll
    for (int pass = 0; pass < 8; pass++) {
        int y = yg + 8 * pass;
        float acc = 0.f;
        #pragma unroll
        for (int kz = 0; kz < 8; kz++) {
            float2 v = sh[y * 8 + kz];
            // Re(v * e^{+i th}) with tw = e^{-i th}:  v.x*tw.x + v.y*tw.y
            acc += v.x * tz[kz].x + v.y * tz[kz].y;
        }
        float r = acc + x2row[y * 32 + z];
        if (do_gelu) r = 0.5f * r * (1.0f + erff(r * 0.70710678118f));
        hrow[y * 32 + z] = r;
    }
}

// ---- head: gelu(h @ fc1 + b1) @ fc2 + b2 ----
__global__ void k_final(const float* __restrict__ h, const float* __restrict__ w1,
                        const float* __restrict__ b1, const float* __restrict__ w2,
                        const float* __restrict__ b2, float* __restrict__ out) {
    __shared__ float psh[8 * 5 * 128];   // 20KB
    int t = threadIdx.x;                 // 256
    int p0 = blockIdx.x * 128;
    int tx = t & 31, ty = t >> 5;
    float acc[16][4];
    #pragma unroll
    for (int a = 0; a < 16; a++)
        #pragma unroll
        for (int bb = 0; bb < 4; bb++) acc[a][bb] = 0.f;
    for (int c = 0; c < 96; c++) {
        float hv[4];
        #pragma unroll
        for (int pp = 0; pp < 4; pp++) hv[pp] = __ldg(&h[(long)c * NP + p0 + tx + 32 * pp]);
        #pragma unroll
        for (int jj = 0; jj < 16; jj++) {
            float wv = __ldg(&w1[c * 128 + ty + 8 * jj]);
            #pragma unroll
            for (int pp = 0; pp < 4; pp++) acc[jj][pp] = fmaf(wv, hv[pp], acc[jj][pp]);
        }
    }
    float acc5[5][4];
    #pragma unroll
    for (int v = 0; v < 5; v++)
        #pragma unroll
        for (int pp = 0; pp < 4; pp++) acc5[v][pp] = 0.f;
    #pragma unroll
    for (int jj = 0; jj < 16; jj++) {
        int j = ty + 8 * jj;
        float bj = __ldg(&b1[j]);
        float wv2[5];
        #pragma unroll
        for (int v = 0; v < 5; v++) wv2[v] = __ldg(&w2[j * 5 + v]);
        #pragma unroll
        for (int pp = 0; pp < 4; pp++) {
            float s = acc[jj][pp] + bj;
            float g = 0.5f * s * (1.0f + erff(s * 0.70710678118f));
            #pragma unroll
            for (int v = 0; v < 5; v++) acc5[v][pp] = fmaf(g, wv2[v], acc5[v][pp]);
        }
    }
    #pragma unroll
    for (int v = 0; v < 5; v++)
        #pragma unroll
        for (int pp = 0; pp < 4; pp++)
            psh[(ty * 5 + v) * 128 + tx + 32 * pp] = acc5[v][pp];
    __syncthreads();
    for (int idx = t; idx < 640; idx += 256) {
        int p = idx / 5, v = idx % 5;
        float s = __ldg(&b2[v]);
        #pragma unroll
        for (int k = 0; k < 8; k++) s += psh[(k * 5 + v) * 128 + p];
        out[(long)(p0 + p) * 5 + v] = s;
    }
}

extern "C" void kernel_launch(void* const* d_in, const int* in_sizes, int n_in,
                              void* d_out, int out_size) {
    const float* x      = (const float*)d_in[0];
    const float* w_spec = (const float*)d_in[1];
    const float* w_skip = (const float*)d_in[2];
    const float* b_skip = (const float*)d_in[3];
    const float* fc0_w  = (const float*)d_in[4];
    const float* fc0_b  = (const float*)d_in[5];
    const float* fc1_w  = (const float*)d_in[6];
    const float* fc1_b  = (const float*)d_in[7];
    const float* fc2_w  = (const float*)d_in[8];
    const float* fc2_b  = (const float*)d_in[9];
    float* out = (float*)d_out;

    float*  ph  = nullptr;  cudaGetSymbolAddress((void**)&ph,  d_h);
    float*  px2 = nullptr;  cudaGetSymbolAddress((void**)&px2, d_x2);
    float2* pS1 = nullptr;  cudaGetSymbolAddress((void**)&pS1, d_S1);
    float2* pS2 = nullptr;  cudaGetSymbolAddress((void**)&pS2, d_S2);
    float2* pS3 = nullptr;  cudaGetSymbolAddress((void**)&pS3, d_S3);
    float2* pG  = nullptr;  cudaGetSymbolAddress((void**)&pG,  d_G);
    float2* pT2 = nullptr;  cudaGetSymbolAddress((void**)&pT2, d_T2);
    float2* pT1 = nullptr;  cudaGetSymbolAddress((void**)&pT1, d_T1);

    k_tw<<<1, 64>>>();
    k_fc0<<<2048, 256>>>(x, fc0_w, fc0_b, ph);
    for (int l = 0; l < 4; l++) {
        k_fwdZ<<<6144, 256>>>(ph, pS1);
        k_fwdY<<<6144, 128>>>(pS1, pS2);
        k_fwdX<<<768, 256>>>(pS2, pS3);
        k_mix<<<384, 256>>>(pS3, w_spec + (long)l * 4 * 96 * 96 * 1024, pG);
        k_invX<<<768, 256>>>(pG, pT2);
        k_invY<<<6144, 256>>>(pT2, pT1);
        k_skip<<<1024, 256>>>(ph, w_skip + l * 96 * 96, b_skip + l * 96, px2);
        k_invZ<<<6144, 256>>>(pT1, px2, ph, (l < 3) ? 1 : 0);
    }
    k_final<<<1024, 256>>>(ph, fc1_w, fc1_b, fc2_w, fc2_b, out);
}